// round 3
// baseline (speedup 1.0000x reference)
#include <cuda_runtime.h>
#include <math.h>

#define N_POI 50000
#define DIM 128
#define E_EDGES 400000
#define GCN_NUM 3
#define BATCH 64
#define LSEQ 100
#define NTOK (BATCH*LSEQ)
#define DIRE (2*E_EDGES)

// ---------------- device scratch (static, no allocations) ----------------
__device__ __align__(16) int   g_cnt[N_POI];
__device__ __align__(16) int   g_rowptr[N_POI+1];
__device__ __align__(16) int   g_rowcur[N_POI];
__device__ __align__(16) float g_dis[N_POI];
__device__ __align__(16) int   g_colidx[DIRE];
__device__ __align__(16) float g_wcsr[DIRE];
__device__ __align__(16) float g_bufA[N_POI*DIM];
__device__ __align__(16) float g_bufB[N_POI*DIM];
__device__ __align__(16) float g_agg[N_POI*DIM];
__device__ __align__(16) float g_qkv[NTOK*3*DIM];
__device__ __align__(16) float g_o[NTOK*DIM];

// packed fp32x2 FMA (Blackwell FFMA2) -- exact fp32 numerics, 2x rate
__device__ __forceinline__ void ffma2(unsigned long long &d,
                                      unsigned long long a,
                                      unsigned long long b){
    asm("fma.rn.f32x2 %0, %1, %2, %0;" : "+l"(d) : "l"(a), "l"(b));
}
__device__ __forceinline__ float pair_sum(unsigned long long v){
    float2 f;
    asm("mov.b64 {%0, %1}, %2;" : "=f"(f.x), "=f"(f.y) : "l"(v));
    return f.x + f.y;
}

// ---------------- CSR build ----------------
__global__ void k_zero_cnt(int* cnt){
    int i = blockIdx.x*256 + threadIdx.x;
    if (i < N_POI) cnt[i] = 0;
}
__global__ void k_hist(const int* __restrict__ e0, const int* __restrict__ e1, int* cnt){
    int e = blockIdx.x*256 + threadIdx.x;
    if (e < E_EDGES){
        atomicAdd(&cnt[e0[e]], 1);
        atomicAdd(&cnt[e1[e]], 1);
    }
}
// single-block exclusive scan over 50k counts; also emits dis = rsqrt(deg)
__global__ void k_scan(const int* __restrict__ cnt, int* __restrict__ rowptr,
                       int* __restrict__ rowcur, float* __restrict__ dis){
    __shared__ int sh[1024];
    int t = threadIdx.x;
    const int CH = (N_POI + 1023)/1024;   // 49
    int base = t*CH;
    int s = 0;
    for (int i = 0; i < CH; i++){
        int idx = base + i;
        if (idx < N_POI) s += cnt[idx];
    }
    sh[t] = s;
    __syncthreads();
    for (int o = 1; o < 1024; o <<= 1){
        int v = (t >= o) ? sh[t-o] : 0;
        __syncthreads();
        sh[t] += v;
        __syncthreads();
    }
    int off = (t == 0) ? 0 : sh[t-1];
    for (int i = 0; i < CH; i++){
        int idx = base + i;
        if (idx < N_POI){
            int c = cnt[idx];
            rowptr[idx] = off;
            rowcur[idx] = off;
            dis[idx] = rsqrtf((float)(c + 1));
            off += c;
        }
    }
    if (t == 1023) rowptr[N_POI] = sh[1023];
}
__global__ void k_scatter(const int* __restrict__ e0, const int* __restrict__ e1,
                          const float* __restrict__ dv, const float* __restrict__ dis,
                          int* rowcur, int* __restrict__ colidx, float* __restrict__ wcsr){
    int e = blockIdx.x*256 + threadIdx.x;
    if (e >= E_EDGES) return;
    int a = e0[e], b = e1[e];
    float d = dv[e];
    float wv = expf(-d*d) * dis[a] * dis[b];
    int p = atomicAdd(&rowcur[a], 1);
    colidx[p] = b; wcsr[p] = wv;
    p = atomicAdd(&rowcur[b], 1);
    colidx[p] = a; wcsr[p] = wv;
}

// ---------------- SpMM: per-row gather (one warp per row), self-loop fused ----------------
__global__ void k_spmm2(const float4* __restrict__ enc4, const int* __restrict__ rowptr,
                        const int* __restrict__ cols, const float* __restrict__ ws,
                        const float* __restrict__ dis, float4* __restrict__ agg4){
    int row = blockIdx.x*8 + (threadIdx.x >> 5);
    int lane = threadIdx.x & 31;
    if (row >= N_POI) return;
    float ds = dis[row];
    float4 x = enc4[row*32 + lane];
    float sl = ds*ds;
    float4 acc = make_float4(sl*x.x, sl*x.y, sl*x.z, sl*x.w);
    int s = __ldg(&rowptr[row]), e = __ldg(&rowptr[row+1]);
    int i = s;
    for (; i + 4 <= e; i += 4){
        int c0 = __ldg(&cols[i]),   c1 = __ldg(&cols[i+1]);
        int c2 = __ldg(&cols[i+2]), c3 = __ldg(&cols[i+3]);
        float w0 = __ldg(&ws[i]),   w1 = __ldg(&ws[i+1]);
        float w2 = __ldg(&ws[i+2]), w3 = __ldg(&ws[i+3]);
        float4 v0 = enc4[c0*32 + lane];
        float4 v1 = enc4[c1*32 + lane];
        float4 v2 = enc4[c2*32 + lane];
        float4 v3 = enc4[c3*32 + lane];
        acc.x = fmaf(w3,v3.x, fmaf(w2,v2.x, fmaf(w1,v1.x, fmaf(w0,v0.x, acc.x))));
        acc.y = fmaf(w3,v3.y, fmaf(w2,v2.y, fmaf(w1,v1.y, fmaf(w0,v0.y, acc.y))));
        acc.z = fmaf(w3,v3.z, fmaf(w2,v2.z, fmaf(w1,v1.z, fmaf(w0,v0.z, acc.z))));
        acc.w = fmaf(w3,v3.w, fmaf(w2,v2.w, fmaf(w1,v1.w, fmaf(w0,v0.w, acc.w))));
    }
    for (; i < e; i++){
        int c = __ldg(&cols[i]);
        float wv = __ldg(&ws[i]);
        float4 v = enc4[c*32 + lane];
        acc.x = fmaf(wv, v.x, acc.x);
        acc.y = fmaf(wv, v.y, acc.y);
        acc.z = fmaf(wv, v.z, acc.z);
        acc.w = fmaf(wv, v.w, acc.w);
    }
    agg4[row*32 + lane] = acc;
}

// ---------------- shared 128x128 FFMA2 microkernel ----------------
// Xs: [128][32] float4 (as ulonglong2), Ws: [128][32] float4 XOR-swizzled.
// acc[r][c] holds packed (even-k, odd-k) partial sums; caller does pair_sum.
__device__ __forceinline__ void mm128_ffma2(const ulonglong2* __restrict__ Xs,
                                            const ulonglong2* __restrict__ Ws,
                                            int tx, int ty,
                                            unsigned long long acc[8][8]){
    #pragma unroll
    for (int r = 0; r < 8; r++)
        #pragma unroll
        for (int c = 0; c < 8; c++) acc[r][c] = 0ull;
    const ulonglong2* Xp = Xs + (ty*8)*32;
    const ulonglong2* Wp = Ws + (tx*8)*32;
    #pragma unroll 2
    for (int k4 = 0; k4 < 32; k4++){
        ulonglong2 xv[8], wv[8];
        #pragma unroll
        for (int r = 0; r < 8; r++) xv[r] = Xp[r*32 + k4];
        int ksw = k4 ^ tx;
        #pragma unroll
        for (int c = 0; c < 8; c++) wv[c] = Wp[c*32 + ksw];
        #pragma unroll
        for (int r = 0; r < 8; r++)
            #pragma unroll
            for (int c = 0; c < 8; c++){
                ffma2(acc[r][c], xv[r].x, wv[c].x);
                ffma2(acc[r][c], xv[r].y, wv[c].y);
            }
    }
}

// ---------------- tiled SGEMM + lrelu + row L2-norm ----------------
__global__ void __launch_bounds__(256, 1)
k_gemm_norm2(const float4* __restrict__ X4, const float* __restrict__ W,
             const float* __restrict__ bias, float4* __restrict__ Y4, int M){
    extern __shared__ float4 sh4[];
    float4* Xs = sh4;            // [128][32]
    float4* Ws = sh4 + 4096;     // [128][32] swizzled: Ws[n*32 + (k4^(n>>3))]
    int tid = threadIdx.x;
    int row0 = blockIdx.x * 128;
    const float4 z4 = make_float4(0.f,0.f,0.f,0.f);
    #pragma unroll
    for (int it = 0; it < 16; it++){
        int idx = tid + it*256;
        int m = idx >> 5, k4 = idx & 31;
        int row = row0 + m;
        Xs[idx] = (row < M) ? X4[row*32 + k4] : z4;
    }
    const float4* W4 = (const float4*)W;
    #pragma unroll
    for (int it = 0; it < 16; it++){
        int idx = tid + it*256;
        int n = idx >> 5, k4 = idx & 31;
        Ws[n*32 + (k4 ^ (n >> 3))] = W4[idx];
    }
    __syncthreads();

    int tx = tid & 15, ty = tid >> 4;
    unsigned long long acc[8][8];
    mm128_ffma2((const ulonglong2*)Xs, (const ulonglong2*)Ws, tx, ty, acc);

    float bj[8];
    #pragma unroll
    for (int c = 0; c < 8; c++) bj[c] = __ldg(&bias[tx*8 + c]);
    #pragma unroll
    for (int r = 0; r < 8; r++){
        float v[8];
        float ss = 0.f;
        #pragma unroll
        for (int c = 0; c < 8; c++){
            float t = pair_sum(acc[r][c]) + bj[c];
            t = (t >= 0.f) ? t : 0.01f*t;
            v[c] = t;
            ss = fmaf(t, t, ss);
        }
        #pragma unroll
        for (int o = 8; o > 0; o >>= 1) ss += __shfl_xor_sync(0xffffffffu, ss, o);
        float inv = 1.0f / fmaxf(sqrtf(ss), 1e-12f);
        int row = row0 + ty*8 + r;
        if (row < M){
            Y4[row*32 + tx*2]     = make_float4(v[0]*inv, v[1]*inv, v[2]*inv, v[3]*inv);
            Y4[row*32 + tx*2 + 1] = make_float4(v[4]*inv, v[5]*inv, v[6]*inv, v[7]*inv);
        }
    }
}

// ---------------- QKV: same tiled GEMM, gathered rows, no norm ----------------
__global__ void __launch_bounds__(256, 1)
k_qkv2(const float4* __restrict__ enc4, const int* __restrict__ xidx,
       const float* __restrict__ inw, const float* __restrict__ inb,
       float4* __restrict__ qkv4){
    extern __shared__ float4 sh4[];
    float4* Xs = sh4;
    float4* Ws = sh4 + 4096;
    int tid = threadIdx.x;
    int row0 = blockIdx.x * 128;
    int nb = blockIdx.y;
    #pragma unroll
    for (int it = 0; it < 16; it++){
        int idx = tid + it*256;
        int m = idx >> 5, k4 = idx & 31;
        int src = __ldg(&xidx[row0 + m]);
        Xs[idx] = enc4[src*32 + k4];
    }
    const float4* W4 = (const float4*)(inw + nb*DIM*DIM);
    #pragma unroll
    for (int it = 0; it < 16; it++){
        int idx = tid + it*256;
        int n = idx >> 5, k4 = idx & 31;
        Ws[n*32 + (k4 ^ (n >> 3))] = W4[idx];
    }
    __syncthreads();

    int tx = tid & 15, ty = tid >> 4;
    unsigned long long acc[8][8];
    mm128_ffma2((const ulonglong2*)Xs, (const ulonglong2*)Ws, tx, ty, acc);

    float bj[8];
    #pragma unroll
    for (int c = 0; c < 8; c++) bj[c] = __ldg(&inb[nb*DIM + tx*8 + c]);
    #pragma unroll
    for (int r = 0; r < 8; r++){
        int t = row0 + ty*8 + r;
        float v[8];
        #pragma unroll
        for (int c = 0; c < 8; c++) v[c] = pair_sum(acc[r][c]) + bj[c];
        qkv4[t*96 + nb*32 + tx*2]     = make_float4(v[0], v[1], v[2], v[3]);
        qkv4[t*96 + nb*32 + tx*2 + 1] = make_float4(v[4], v[5], v[6], v[7]);
    }
}

// ---------------- attention: one block per (b, h) ----------------
__global__ void k_attn(const float* __restrict__ qkv, float* __restrict__ o){
    __shared__ float sq[LSEQ*16], sk[LSEQ*16], sv[LSEQ*16];
    __shared__ float sp[32*LSEQ];
    int b = blockIdx.x, h = blockIdx.y;
    int tid = threadIdx.x;
    for (int idx = tid; idx < LSEQ*16; idx += 128){
        int t = idx >> 4, d = idx & 15;
        int base = (b*LSEQ + t)*(3*DIM) + h*16 + d;
        sq[idx] = qkv[base];
        sk[idx] = qkv[base + DIM];
        sv[idx] = qkv[base + 2*DIM];
    }
    __syncthreads();
    int lane = tid & 31, warp = tid >> 5;
    for (int q0 = 0; q0 < LSEQ; q0 += 32){
        int nq = min(32, LSEQ - q0);
        for (int idx = tid; idx < nq*LSEQ; idx += 128){
            int qi = idx / LSEQ, j = idx - qi*LSEQ;
            const float* qp = &sq[(q0 + qi)*16];
            const float* kp = &sk[j*16];
            float s = 0.0f;
            #pragma unroll
            for (int d = 0; d < 16; d++) s += qp[d]*kp[d];
            sp[idx] = s*0.25f;   // 1/sqrt(16)
        }
        __syncthreads();
        for (int qi = warp; qi < nq; qi += 4){
            float v[4];
            float m = -1e30f;
            #pragma unroll
            for (int jj = 0; jj < 4; jj++){
                int j = lane + jj*32;
                v[jj] = (j < LSEQ) ? sp[qi*LSEQ + j] : -1e30f;
                m = fmaxf(m, v[jj]);
            }
            #pragma unroll
            for (int t = 16; t > 0; t >>= 1) m = fmaxf(m, __shfl_xor_sync(0xffffffffu, m, t));
            float s = 0.0f;
            #pragma unroll
            for (int jj = 0; jj < 4; jj++){
                int j = lane + jj*32;
                float p = (j < LSEQ) ? expf(v[jj] - m) : 0.0f;
                v[jj] = p; s += p;
            }
            #pragma unroll
            for (int t = 16; t > 0; t >>= 1) s += __shfl_xor_sync(0xffffffffu, s, t);
            float inv = 1.0f / s;
            #pragma unroll
            for (int jj = 0; jj < 4; jj++){
                int j = lane + jj*32;
                if (j < LSEQ) sp[qi*LSEQ + j] = v[jj]*inv;
            }
        }
        __syncthreads();
        for (int idx = tid; idx < nq*16; idx += 128){
            int qi = idx >> 4, d = idx & 15;
            float acc = 0.0f;
            for (int j = 0; j < LSEQ; j++) acc += sp[qi*LSEQ + j]*sv[j*16 + d];
            o[(b*LSEQ + q0 + qi)*DIM + h*16 + d] = acc;
        }
        __syncthreads();
    }
}

// ---------------- mean over L + out-projection (they commute) + target gather ----------------
__global__ void k_tail(const float* __restrict__ o, const float* __restrict__ ow,
                       const float* __restrict__ ob, const float* __restrict__ enc,
                       const int* __restrict__ pidx, float* __restrict__ out){
    __shared__ float sx[DIM];
    int b = blockIdx.x, j = threadIdx.x;
    float s = 0.0f;
    for (int i = 0; i < LSEQ; i++) s += o[(b*LSEQ + i)*DIM + j];
    sx[j] = s * (1.0f/LSEQ);
    __syncthreads();
    float acc = ob[j];
    #pragma unroll 4
    for (int k = 0; k < DIM; k++) acc += sx[k]*ow[j*DIM + k];
    out[b*DIM + j] = acc;
    out[BATCH*DIM + b*DIM + j] = enc[pidx[b]*DIM + j];
}

// ---------------- host launch ----------------
extern "C" void kernel_launch(void* const* d_in, const int* in_sizes, int n_in,
                              void* d_out, int out_size){
    const float* embeds = (const float*)d_in[0];
    const float* gcnW   = (const float*)d_in[1];
    const float* gcnb   = (const float*)d_in[2];
    const float* inw    = (const float*)d_in[3];
    const float* inb    = (const float*)d_in[4];
    const float* ow     = (const float*)d_in[5];
    const float* ob     = (const float*)d_in[6];
    const float* dv     = (const float*)d_in[7];
    const int*   edges  = (const int*)d_in[8];
    const int*   xidx   = (const int*)d_in[9];
    const int*   pidx   = (const int*)d_in[10];
    const int* e0 = edges;
    const int* e1 = edges + E_EDGES;
    float* out = (float*)d_out;

    int *cnt, *rowptr, *rowcur, *colidx;
    float *dis, *wcsr, *agg, *bA, *bB, *qkv, *obuf;
    cudaGetSymbolAddress((void**)&cnt,    g_cnt);
    cudaGetSymbolAddress((void**)&rowptr, g_rowptr);
    cudaGetSymbolAddress((void**)&rowcur, g_rowcur);
    cudaGetSymbolAddress((void**)&dis,    g_dis);
    cudaGetSymbolAddress((void**)&colidx, g_colidx);
    cudaGetSymbolAddress((void**)&wcsr,   g_wcsr);
    cudaGetSymbolAddress((void**)&agg,    g_agg);
    cudaGetSymbolAddress((void**)&bA,     g_bufA);
    cudaGetSymbolAddress((void**)&bB,     g_bufB);
    cudaGetSymbolAddress((void**)&qkv,    g_qkv);
    cudaGetSymbolAddress((void**)&obuf,   g_o);

    const int smem_gemm = 2*4096*(int)sizeof(float4);   // 131072
    cudaFuncSetAttribute(k_gemm_norm2, cudaFuncAttributeMaxDynamicSharedMemorySize, smem_gemm);
    cudaFuncSetAttribute(k_qkv2,       cudaFuncAttributeMaxDynamicSharedMemorySize, smem_gemm);

    // CSR build
    k_zero_cnt<<<(N_POI+255)/256, 256>>>(cnt);
    k_hist<<<(E_EDGES+255)/256, 256>>>(e0, e1, cnt);
    k_scan<<<1, 1024>>>(cnt, rowptr, rowcur, dis);
    k_scatter<<<(E_EDGES+255)/256, 256>>>(e0, e1, dv, dis, rowcur, colidx, wcsr);

    // 3 GCN layers
    const float* enc_in = embeds;
    float* outs[GCN_NUM] = {bA, bB, bA};
    for (int i = 0; i < GCN_NUM; i++){
        k_spmm2<<<(N_POI+7)/8, 256>>>((const float4*)enc_in, rowptr, colidx, wcsr, dis,
                                       (float4*)agg);
        k_gemm_norm2<<<(N_POI+127)/128, 256, smem_gemm>>>(
            (const float4*)agg, gcnW + i*DIM*DIM, gcnb + i*DIM, (float4*)outs[i], N_POI);
        enc_in = outs[i];
    }
    const float* encF = enc_in;  // g_bufA

    // attention
    k_qkv2<<<dim3(NTOK/128, 3), 256, smem_gemm>>>((const float4*)encF, xidx, inw, inb,
                                                  (float4*)qkv);
    k_attn<<<dim3(BATCH, 8), 128>>>(qkv, obuf);
    k_tail<<<BATCH, 128>>>(obuf, ow, ob, encF, pidx, out);
}

// round 5
// speedup vs baseline: 1.1436x; 1.1436x over previous
#include <cuda_runtime.h>
#include <math.h>
#include <stdint.h>

#define N_POI 50000
#define DIM 128
#define E_EDGES 400000
#define GCN_NUM 3
#define BATCH 64
#define LSEQ 100
#define NTOK (BATCH*LSEQ)
#define DIRE (2*E_EDGES)

// ---------------- device scratch (static, no allocations) ----------------
__device__ __align__(16) int   g_cnt[N_POI];
__device__ __align__(16) int   g_rowptr[N_POI+1];
__device__ __align__(16) int   g_rowcur[N_POI];
__device__ __align__(16) float g_dis[N_POI];
__device__ __align__(16) int   g_colidx[DIRE];
__device__ __align__(16) float g_wcsr[DIRE];
__device__ __align__(16) float g_bufA[N_POI*DIM];
__device__ __align__(16) float g_bufB[N_POI*DIM];
__device__ __align__(16) float g_agg[N_POI*DIM];
__device__ __align__(16) float g_qkv[NTOK*3*DIM];
__device__ __align__(16) float g_o[NTOK*DIM];

// tf32 helpers (base-target safe: mma.sync is sm_80+ PTX)
__device__ __forceinline__ uint32_t to_tf32(float x){
    uint32_t u;
    asm("cvt.rna.tf32.f32 %0, %1;" : "=r"(u) : "f"(x));
    return u;
}
__device__ __forceinline__ void mma_tf32(float* d, const uint32_t* a, const uint32_t* b){
    asm volatile("mma.sync.aligned.m16n8k8.row.col.f32.tf32.tf32.f32 "
        "{%0,%1,%2,%3}, {%4,%5,%6,%7}, {%8,%9}, {%0,%1,%2,%3};"
        : "+f"(d[0]), "+f"(d[1]), "+f"(d[2]), "+f"(d[3])
        : "r"(a[0]), "r"(a[1]), "r"(a[2]), "r"(a[3]), "r"(b[0]), "r"(b[1]));
}

// ---------------- CSR build ----------------
__global__ void k_zero_cnt(int* cnt){
    int i = blockIdx.x*256 + threadIdx.x;
    if (i < N_POI) cnt[i] = 0;
}
__global__ void k_hist(const int* __restrict__ e0, const int* __restrict__ e1, int* cnt){
    int e = blockIdx.x*256 + threadIdx.x;
    if (e < E_EDGES){
        atomicAdd(&cnt[e0[e]], 1);
        atomicAdd(&cnt[e1[e]], 1);
    }
}
__global__ void k_scan(const int* __restrict__ cnt, int* __restrict__ rowptr,
                       int* __restrict__ rowcur, float* __restrict__ dis){
    __shared__ int sh[1024];
    int t = threadIdx.x;
    const int CH = (N_POI + 1023)/1024;
    int base = t*CH;
    int s = 0;
    for (int i = 0; i < CH; i++){
        int idx = base + i;
        if (idx < N_POI) s += cnt[idx];
    }
    sh[t] = s;
    __syncthreads();
    for (int o = 1; o < 1024; o <<= 1){
        int v = (t >= o) ? sh[t-o] : 0;
        __syncthreads();
        sh[t] += v;
        __syncthreads();
    }
    int off = (t == 0) ? 0 : sh[t-1];
    for (int i = 0; i < CH; i++){
        int idx = base + i;
        if (idx < N_POI){
            int c = cnt[idx];
            rowptr[idx] = off;
            rowcur[idx] = off;
            dis[idx] = rsqrtf((float)(c + 1));
            off += c;
        }
    }
    if (t == 1023) rowptr[N_POI] = sh[1023];
}
__global__ void k_scatter(const int* __restrict__ e0, const int* __restrict__ e1,
                          const float* __restrict__ dv, const float* __restrict__ dis,
                          int* rowcur, int* __restrict__ colidx, float* __restrict__ wcsr){
    int e = blockIdx.x*256 + threadIdx.x;
    if (e >= E_EDGES) return;
    int a = e0[e], b = e1[e];
    float d = dv[e];
    float wv = expf(-d*d) * dis[a] * dis[b];
    int p = atomicAdd(&rowcur[a], 1);
    colidx[p] = b; wcsr[p] = wv;
    p = atomicAdd(&rowcur[b], 1);
    colidx[p] = a; wcsr[p] = wv;
}

// ---------------- SpMM: per-row gather (one warp per row), self-loop fused ----------------
__global__ void k_spmm2(const float4* __restrict__ enc4, const int* __restrict__ rowptr,
                        const int* __restrict__ cols, const float* __restrict__ ws,
                        const float* __restrict__ dis, float4* __restrict__ agg4){
    int row = blockIdx.x*8 + (threadIdx.x >> 5);
    int lane = threadIdx.x & 31;
    if (row >= N_POI) return;
    float ds = dis[row];
    float4 x = enc4[row*32 + lane];
    float sl = ds*ds;
    float4 acc = make_float4(sl*x.x, sl*x.y, sl*x.z, sl*x.w);
    int s = __ldg(&rowptr[row]), e = __ldg(&rowptr[row+1]);
    int i = s;
    for (; i + 4 <= e; i += 4){
        int c0 = __ldg(&cols[i]),   c1 = __ldg(&cols[i+1]);
        int c2 = __ldg(&cols[i+2]), c3 = __ldg(&cols[i+3]);
        float w0 = __ldg(&ws[i]),   w1 = __ldg(&ws[i+1]);
        float w2 = __ldg(&ws[i+2]), w3 = __ldg(&ws[i+3]);
        float4 v0 = enc4[c0*32 + lane];
        float4 v1 = enc4[c1*32 + lane];
        float4 v2 = enc4[c2*32 + lane];
        float4 v3 = enc4[c3*32 + lane];
        acc.x = fmaf(w3,v3.x, fmaf(w2,v2.x, fmaf(w1,v1.x, fmaf(w0,v0.x, acc.x))));
        acc.y = fmaf(w3,v3.y, fmaf(w2,v2.y, fmaf(w1,v1.y, fmaf(w0,v0.y, acc.y))));
        acc.z = fmaf(w3,v3.z, fmaf(w2,v2.z, fmaf(w1,v1.z, fmaf(w0,v0.z, acc.z))));
        acc.w = fmaf(w3,v3.w, fmaf(w2,v2.w, fmaf(w1,v1.w, fmaf(w0,v0.w, acc.w))));
    }
    for (; i < e; i++){
        int c = __ldg(&cols[i]);
        float wv = __ldg(&ws[i]);
        float4 v = enc4[c*32 + lane];
        acc.x = fmaf(wv, v.x, acc.x);
        acc.y = fmaf(wv, v.y, acc.y);
        acc.z = fmaf(wv, v.z, acc.z);
        acc.w = fmaf(wv, v.w, acc.w);
    }
    agg4[row*32 + lane] = acc;
}

// ================= tf32 mma.sync GEMM + lrelu + row L2-norm =================
// 128x128 tile, K=128. 8 warps: warp_m = wid&1 (64 rows), warp_n = wid>>1 (32 cols).
#define GP 132   // smem pitch in floats (conflict-free frag loads)
__global__ void __launch_bounds__(256, 1)
k_gemm_tf32(const float4* __restrict__ X4, const float* __restrict__ W,
            const float* __restrict__ bias, float* __restrict__ Y, int M){
    extern __shared__ uint32_t sh[];
    uint32_t* As = sh;              // [128][GP] tf32 bits
    uint32_t* Bs = sh + 128*GP;     // [128][GP] tf32 bits (Bs[n][k] = W[n][k])
    __shared__ float ssred[128][4];
    __shared__ float sscale[128];
    int tid = threadIdx.x;
    int row0 = blockIdx.x * 128;

    // stage + convert
    const float4* W4 = (const float4*)W;
    for (int i = tid; i < 128*32; i += 256){
        int r = i >> 5, c4 = i & 31;
        int grow = row0 + r;
        float4 v = (grow < M) ? X4[grow*32 + c4] : make_float4(0.f,0.f,0.f,0.f);
        float4 wv = W4[i];
        int base = r*GP + c4*4;
        As[base+0] = to_tf32(v.x);  As[base+1] = to_tf32(v.y);
        As[base+2] = to_tf32(v.z);  As[base+3] = to_tf32(v.w);
        Bs[base+0] = to_tf32(wv.x); Bs[base+1] = to_tf32(wv.y);
        Bs[base+2] = to_tf32(wv.z); Bs[base+3] = to_tf32(wv.w);
    }
    __syncthreads();

    int wid = tid >> 5, lane = tid & 31;
    int wm = wid & 1, wn = wid >> 1;
    int m_base = wm*64, n_base = wn*32;
    int qr = lane >> 2, qc = lane & 3;

    float acc[4][4][4];
    #pragma unroll
    for (int mi = 0; mi < 4; mi++)
        #pragma unroll
        for (int ni = 0; ni < 4; ni++)
            #pragma unroll
            for (int j = 0; j < 4; j++) acc[mi][ni][j] = 0.f;

    #pragma unroll 2
    for (int k0 = 0; k0 < 128; k0 += 8){
        uint32_t a[4][4];
        #pragma unroll
        for (int mi = 0; mi < 4; mi++){
            const uint32_t* ap = As + (m_base + mi*16 + qr)*GP + k0 + qc;
            a[mi][0] = ap[0];
            a[mi][1] = ap[8*GP];
            a[mi][2] = ap[4];
            a[mi][3] = ap[8*GP + 4];
        }
        uint32_t b[4][2];
        #pragma unroll
        for (int ni = 0; ni < 4; ni++){
            const uint32_t* bp = Bs + (n_base + ni*8 + qr)*GP + k0 + qc;
            b[ni][0] = bp[0];
            b[ni][1] = bp[4];
        }
        #pragma unroll
        for (int mi = 0; mi < 4; mi++)
            #pragma unroll
            for (int ni = 0; ni < 4; ni++)
                mma_tf32(acc[mi][ni], a[mi], b[ni]);
    }

    // epilogue: bias + lrelu + per-row sum of squares
    float2 bv[4];
    #pragma unroll
    for (int ni = 0; ni < 4; ni++)
        bv[ni] = *(const float2*)&bias[n_base + ni*8 + qc*2];

    float ss[4][2];
    #pragma unroll
    for (int mi = 0; mi < 4; mi++){ ss[mi][0] = 0.f; ss[mi][1] = 0.f; }
    #pragma unroll
    for (int mi = 0; mi < 4; mi++)
        #pragma unroll
        for (int ni = 0; ni < 4; ni++){
            float* d = acc[mi][ni];
            float t0 = d[0] + bv[ni].x, t1 = d[1] + bv[ni].y;
            float t2 = d[2] + bv[ni].x, t3 = d[3] + bv[ni].y;
            t0 = (t0 >= 0.f) ? t0 : 0.01f*t0;
            t1 = (t1 >= 0.f) ? t1 : 0.01f*t1;
            t2 = (t2 >= 0.f) ? t2 : 0.01f*t2;
            t3 = (t3 >= 0.f) ? t3 : 0.01f*t3;
            d[0] = t0; d[1] = t1; d[2] = t2; d[3] = t3;
            ss[mi][0] = fmaf(t0,t0, fmaf(t1,t1, ss[mi][0]));
            ss[mi][1] = fmaf(t2,t2, fmaf(t3,t3, ss[mi][1]));
        }
    #pragma unroll
    for (int mi = 0; mi < 4; mi++)
        #pragma unroll
        for (int hf = 0; hf < 2; hf++){
            float v = ss[mi][hf];
            v += __shfl_xor_sync(0xffffffffu, v, 1);
            v += __shfl_xor_sync(0xffffffffu, v, 2);
            if (qc == 0) ssred[m_base + mi*16 + qr + hf*8][wn] = v;
        }
    __syncthreads();
    if (tid < 128){
        float t = ssred[tid][0] + ssred[tid][1] + ssred[tid][2] + ssred[tid][3];
        sscale[tid] = 1.0f / fmaxf(sqrtf(t), 1e-12f);
    }
    __syncthreads();

    #pragma unroll
    for (int mi = 0; mi < 4; mi++){
        int lr0 = m_base + mi*16 + qr;
        int lr1 = lr0 + 8;
        float s0 = sscale[lr0], s1 = sscale[lr1];
        int r0 = row0 + lr0, r1 = row0 + lr1;
        #pragma unroll
        for (int ni = 0; ni < 4; ni++){
            float* d = acc[mi][ni];
            int col = n_base + ni*8 + qc*2;
            if (r0 < M) *(float2*)&Y[r0*DIM + col] = make_float2(d[0]*s0, d[1]*s0);
            if (r1 < M) *(float2*)&Y[r1*DIM + col] = make_float2(d[2]*s1, d[3]*s1);
        }
    }
}

// ---------------- QKV: scalar tiled GEMM (proven R2 version) ----------------
__global__ void __launch_bounds__(256, 1)
k_qkv2(const float4* __restrict__ enc4, const int* __restrict__ xidx,
       const float* __restrict__ inw, const float* __restrict__ inb,
       float4* __restrict__ qkv4){
    extern __shared__ float4 sh4[];
    float4* Xs = sh4;
    float4* Ws = sh4 + 4096;
    int tid = threadIdx.x;
    int row0 = blockIdx.x * 128;
    int nb = blockIdx.y;
    #pragma unroll
    for (int it = 0; it < 16; it++){
        int idx = tid + it*256;
        int m = idx >> 5, k4 = idx & 31;
        int src = __ldg(&xidx[row0 + m]);
        Xs[idx] = enc4[src*32 + k4];
    }
    const float4* W4 = (const float4*)(inw + nb*DIM*DIM);
    #pragma unroll
    for (int it = 0; it < 16; it++){
        int idx = tid + it*256;
        int n = idx >> 5, k4 = idx & 31;
        Ws[n*32 + (k4 ^ (n >> 3))] = W4[idx];
    }
    __syncthreads();

    int tx = tid & 15, ty = tid >> 4;
    float acc[8][8];
    #pragma unroll
    for (int r = 0; r < 8; r++)
        #pragma unroll
        for (int c = 0; c < 8; c++) acc[r][c] = 0.f;

    const float4* Xp = Xs + (ty*8)*32;
    const float4* Wp = Ws + (tx*8)*32;
    #pragma unroll 2
    for (int k4 = 0; k4 < 32; k4++){
        float4 xv[8], wv[8];
        #pragma unroll
        for (int r = 0; r < 8; r++) xv[r] = Xp[r*32 + k4];
        int ksw = k4 ^ tx;
        #pragma unroll
        for (int c = 0; c < 8; c++) wv[c] = Wp[c*32 + ksw];
        #pragma unroll
        for (int r = 0; r < 8; r++)
            #pragma unroll
            for (int c = 0; c < 8; c++){
                acc[r][c] = fmaf(xv[r].x, wv[c].x, acc[r][c]);
                acc[r][c] = fmaf(xv[r].y, wv[c].y, acc[r][c]);
                acc[r][c] = fmaf(xv[r].z, wv[c].z, acc[r][c]);
                acc[r][c] = fmaf(xv[r].w, wv[c].w, acc[r][c]);
            }
    }

    float bj[8];
    #pragma unroll
    for (int c = 0; c < 8; c++) bj[c] = __ldg(&inb[nb*DIM + tx*8 + c]);
    #pragma unroll
    for (int r = 0; r < 8; r++){
        int t = row0 + ty*8 + r;
        qkv4[t*96 + nb*32 + tx*2]     = make_float4(acc[r][0]+bj[0], acc[r][1]+bj[1], acc[r][2]+bj[2], acc[r][3]+bj[3]);
        qkv4[t*96 + nb*32 + tx*2 + 1] = make_float4(acc[r][4]+bj[4], acc[r][5]+bj[5], acc[r][6]+bj[6], acc[r][7]+bj[7]);
    }
}

// ---------------- attention: one block per (b, h) ----------------
__global__ void k_attn(const float* __restrict__ qkv, float* __restrict__ o){
    __shared__ float sq[LSEQ*16], sk[LSEQ*16], sv[LSEQ*16];
    __shared__ float sp[32*LSEQ];
    int b = blockIdx.x, h = blockIdx.y;
    int tid = threadIdx.x;
    for (int idx = tid; idx < LSEQ*16; idx += 128){
        int t = idx >> 4, d = idx & 15;
        int base = (b*LSEQ + t)*(3*DIM) + h*16 + d;
        sq[idx] = qkv[base];
        sk[idx] = qkv[base + DIM];
        sv[idx] = qkv[base + 2*DIM];
    }
    __syncthreads();
    int lane = tid & 31, warp = tid >> 5;
    for (int q0 = 0; q0 < LSEQ; q0 += 32){
        int nq = min(32, LSEQ - q0);
        for (int idx = tid; idx < nq*LSEQ; idx += 128){
            int qi = idx / LSEQ, j = idx - qi*LSEQ;
            const float* qp = &sq[(q0 + qi)*16];
            const float* kp = &sk[j*16];
            float s = 0.0f;
            #pragma unroll
            for (int d = 0; d < 16; d++) s += qp[d]*kp[d];
            sp[idx] = s*0.25f;
        }
        __syncthreads();
        for (int qi = warp; qi < nq; qi += 4){
            float v[4];
            float m = -1e30f;
            #pragma unroll
            for (int jj = 0; jj < 4; jj++){
                int j = lane + jj*32;
                v[jj] = (j < LSEQ) ? sp[qi*LSEQ + j] : -1e30f;
                m = fmaxf(m, v[jj]);
            }
            #pragma unroll
            for (int t = 16; t > 0; t >>= 1) m = fmaxf(m, __shfl_xor_sync(0xffffffffu, m, t));
            float s = 0.0f;
            #pragma unroll
            for (int jj = 0; jj < 4; jj++){
                int j = lane + jj*32;
                float p = (j < LSEQ) ? expf(v[jj] - m) : 0.0f;
                v[jj] = p; s += p;
            }
            #pragma unroll
            for (int t = 16; t > 0; t >>= 1) s += __shfl_xor_sync(0xffffffffu, s, t);
            float inv = 1.0f / s;
            #pragma unroll
            for (int jj = 0; jj < 4; jj++){
                int j = lane + jj*32;
                if (j < LSEQ) sp[qi*LSEQ + j] = v[jj]*inv;
            }
        }
        __syncthreads();
        for (int idx = tid; idx < nq*16; idx += 128){
            int qi = idx >> 4, d = idx & 15;
            float acc = 0.0f;
            for (int j = 0; j < LSEQ; j++) acc += sp[qi*LSEQ + j]*sv[j*16 + d];
            o[(b*LSEQ + q0 + qi)*DIM + h*16 + d] = acc;
        }
        __syncthreads();
    }
}

// ---------------- mean over L + out-projection + target gather ----------------
__global__ void k_tail(const float* __restrict__ o, const float* __restrict__ ow,
                       const float* __restrict__ ob, const float* __restrict__ enc,
                       const int* __restrict__ pidx, float* __restrict__ out){
    __shared__ float sx[DIM];
    int b = blockIdx.x, j = threadIdx.x;
    float s = 0.0f;
    for (int i = 0; i < LSEQ; i++) s += o[(b*LSEQ + i)*DIM + j];
    sx[j] = s * (1.0f/LSEQ);
    __syncthreads();
    float acc = ob[j];
    #pragma unroll 4
    for (int k = 0; k < DIM; k++) acc += sx[k]*ow[j*DIM + k];
    out[b*DIM + j] = acc;
    out[BATCH*DIM + b*DIM + j] = enc[pidx[b]*DIM + j];
}

// ---------------- host launch ----------------
extern "C" void kernel_launch(void* const* d_in, const int* in_sizes, int n_in,
                              void* d_out, int out_size){
    const float* embeds = (const float*)d_in[0];
    const float* gcnW   = (const float*)d_in[1];
    const float* gcnb   = (const float*)d_in[2];
    const float* inw    = (const float*)d_in[3];
    const float* inb    = (const float*)d_in[4];
    const float* ow     = (const float*)d_in[5];
    const float* ob     = (const float*)d_in[6];
    const float* dv     = (const float*)d_in[7];
    const int*   edges  = (const int*)d_in[8];
    const int*   xidx   = (const int*)d_in[9];
    const int*   pidx   = (const int*)d_in[10];
    const int* e0 = edges;
    const int* e1 = edges + E_EDGES;
    float* out = (float*)d_out;

    int *cnt, *rowptr, *rowcur, *colidx;
    float *dis, *wcsr, *agg, *bA, *bB, *qkv, *obuf;
    cudaGetSymbolAddress((void**)&cnt,    g_cnt);
    cudaGetSymbolAddress((void**)&rowptr, g_rowptr);
    cudaGetSymbolAddress((void**)&rowcur, g_rowcur);
    cudaGetSymbolAddress((void**)&dis,    g_dis);
    cudaGetSymbolAddress((void**)&colidx, g_colidx);
    cudaGetSymbolAddress((void**)&wcsr,   g_wcsr);
    cudaGetSymbolAddress((void**)&agg,    g_agg);
    cudaGetSymbolAddress((void**)&bA,     g_bufA);
    cudaGetSymbolAddress((void**)&bB,     g_bufB);
    cudaGetSymbolAddress((void**)&qkv,    g_qkv);
    cudaGetSymbolAddress((void**)&obuf,   g_o);

    const int smem_qkv  = 2*4096*(int)sizeof(float4);      // 131072
    const int smem_gemm = 2*128*GP*(int)sizeof(uint32_t);  // 135168
    cudaFuncSetAttribute(k_gemm_tf32, cudaFuncAttributeMaxDynamicSharedMemorySize, smem_gemm);
    cudaFuncSetAttribute(k_qkv2,      cudaFuncAttributeMaxDynamicSharedMemorySize, smem_qkv);

    // CSR build
    k_zero_cnt<<<(N_POI+255)/256, 256>>>(cnt);
    k_hist<<<(E_EDGES+255)/256, 256>>>(e0, e1, cnt);
    k_scan<<<1, 1024>>>(cnt, rowptr, rowcur, dis);
    k_scatter<<<(E_EDGES+255)/256, 256>>>(e0, e1, dv, dis, rowcur, colidx, wcsr);

    // 3 GCN layers
    const float* enc_in = embeds;
    float* outs[GCN_NUM] = {bA, bB, bA};
    for (int i = 0; i < GCN_NUM; i++){
        k_spmm2<<<(N_POI+7)/8, 256>>>((const float4*)enc_in, rowptr, colidx, wcsr, dis,
                                       (float4*)agg);
        k_gemm_tf32<<<(N_POI+127)/128, 256, smem_gemm>>>(
            (const float4*)agg, gcnW + i*DIM*DIM, gcnb + i*DIM, outs[i], N_POI);
        enc_in = outs[i];
    }
    const float* encF = enc_in;  // g_bufA

    // attention
    k_qkv2<<<dim3(NTOK/128, 3), 256, smem_qkv>>>((const float4*)encF, xidx, inw, inb,
                                                 (float4*)qkv);
    k_attn<<<dim3(BATCH, 8), 128>>>(qkv, obuf);
    k_tail<<<BATCH, 128>>>(obuf, ow, ob, encF, pidx, out);
}

// round 6
// speedup vs baseline: 1.2061x; 1.0547x over previous
#include <cuda_runtime.h>
#include <math.h>
#include <stdint.h>

#define N_POI 50000
#define DIM 128
#define E_EDGES 400000
#define GCN_NUM 3
#define BATCH 64
#define LSEQ 100
#define NTOK (BATCH*LSEQ)
#define DIRE (2*E_EDGES)

// ---------------- device scratch (static, no allocations) ----------------
__device__ __align__(16) int   g_cnt[N_POI];
__device__ __align__(16) int   g_rowptr[N_POI+1];
__device__ __align__(16) int   g_rowcur[N_POI];
__device__ __align__(16) float g_dis[N_POI];
__device__ __align__(16) int   g_colidx[DIRE];
__device__ __align__(16) float g_wcsr[DIRE];
__device__ __align__(16) float g_bufA[N_POI*DIM];
__device__ __align__(16) float g_bufB[N_POI*DIM];
__device__ __align__(16) float g_agg[N_POI*DIM];
__device__ __align__(16) float g_qkv[NTOK*3*DIM];
__device__ __align__(16) float g_o[NTOK*DIM];

// tf32 helpers (base-target safe: mma.sync is sm_80+ PTX)
__device__ __forceinline__ uint32_t to_tf32(float x){
    uint32_t u;
    asm("cvt.rna.tf32.f32 %0, %1;" : "=r"(u) : "f"(x));
    return u;
}
__device__ __forceinline__ void mma_tf32(float* d, const uint32_t* a, const uint32_t* b){
    asm volatile("mma.sync.aligned.m16n8k8.row.col.f32.tf32.tf32.f32 "
        "{%0,%1,%2,%3}, {%4,%5,%6,%7}, {%8,%9}, {%0,%1,%2,%3};"
        : "+f"(d[0]), "+f"(d[1]), "+f"(d[2]), "+f"(d[3])
        : "r"(a[0]), "r"(a[1]), "r"(a[2]), "r"(a[3]), "r"(b[0]), "r"(b[1]));
}

// ---------------- CSR build ----------------
__global__ void k_zero_cnt(int* cnt){
    int i = blockIdx.x*256 + threadIdx.x;
    if (i < N_POI) cnt[i] = 0;
}
__global__ void k_hist(const int* __restrict__ e0, const int* __restrict__ e1, int* cnt){
    int e = blockIdx.x*256 + threadIdx.x;
    if (e < E_EDGES){
        atomicAdd(&cnt[e0[e]], 1);
        atomicAdd(&cnt[e1[e]], 1);
    }
}
__global__ void k_scan(const int* __restrict__ cnt, int* __restrict__ rowptr,
                       int* __restrict__ rowcur, float* __restrict__ dis){
    __shared__ int sh[1024];
    int t = threadIdx.x;
    const int CH = (N_POI + 1023)/1024;
    int base = t*CH;
    int s = 0;
    for (int i = 0; i < CH; i++){
        int idx = base + i;
        if (idx < N_POI) s += cnt[idx];
    }
    sh[t] = s;
    __syncthreads();
    for (int o = 1; o < 1024; o <<= 1){
        int v = (t >= o) ? sh[t-o] : 0;
        __syncthreads();
        sh[t] += v;
        __syncthreads();
    }
    int off = (t == 0) ? 0 : sh[t-1];
    for (int i = 0; i < CH; i++){
        int idx = base + i;
        if (idx < N_POI){
            int c = cnt[idx];
            rowptr[idx] = off;
            rowcur[idx] = off;
            dis[idx] = rsqrtf((float)(c + 1));
            off += c;
        }
    }
    if (t == 1023) rowptr[N_POI] = sh[1023];
}
__global__ void k_scatter(const int* __restrict__ e0, const int* __restrict__ e1,
                          const float* __restrict__ dv, const float* __restrict__ dis,
                          int* rowcur, int* __restrict__ colidx, float* __restrict__ wcsr){
    int e = blockIdx.x*256 + threadIdx.x;
    if (e >= E_EDGES) return;
    int a = e0[e], b = e1[e];
    float d = dv[e];
    float wv = expf(-d*d) * dis[a] * dis[b];
    int p = atomicAdd(&rowcur[a], 1);
    colidx[p] = b; wcsr[p] = wv;
    p = atomicAdd(&rowcur[b], 1);
    colidx[p] = a; wcsr[p] = wv;
}

// ---------------- SpMM: per-row gather (one warp per row), self-loop fused ----------------
__global__ void k_spmm2(const float4* __restrict__ enc4, const int* __restrict__ rowptr,
                        const int* __restrict__ cols, const float* __restrict__ ws,
                        const float* __restrict__ dis, float4* __restrict__ agg4){
    int row = blockIdx.x*8 + (threadIdx.x >> 5);
    int lane = threadIdx.x & 31;
    if (row >= N_POI) return;
    float ds = dis[row];
    float4 x = enc4[row*32 + lane];
    float sl = ds*ds;
    float4 acc = make_float4(sl*x.x, sl*x.y, sl*x.z, sl*x.w);
    int s = __ldg(&rowptr[row]), e = __ldg(&rowptr[row+1]);
    int i = s;
    for (; i + 4 <= e; i += 4){
        int c0 = __ldg(&cols[i]),   c1 = __ldg(&cols[i+1]);
        int c2 = __ldg(&cols[i+2]), c3 = __ldg(&cols[i+3]);
        float w0 = __ldg(&ws[i]),   w1 = __ldg(&ws[i+1]);
        float w2 = __ldg(&ws[i+2]), w3 = __ldg(&ws[i+3]);
        float4 v0 = enc4[c0*32 + lane];
        float4 v1 = enc4[c1*32 + lane];
        float4 v2 = enc4[c2*32 + lane];
        float4 v3 = enc4[c3*32 + lane];
        acc.x = fmaf(w3,v3.x, fmaf(w2,v2.x, fmaf(w1,v1.x, fmaf(w0,v0.x, acc.x))));
        acc.y = fmaf(w3,v3.y, fmaf(w2,v2.y, fmaf(w1,v1.y, fmaf(w0,v0.y, acc.y))));
        acc.z = fmaf(w3,v3.z, fmaf(w2,v2.z, fmaf(w1,v1.z, fmaf(w0,v0.z, acc.z))));
        acc.w = fmaf(w3,v3.w, fmaf(w2,v2.w, fmaf(w1,v1.w, fmaf(w0,v0.w, acc.w))));
    }
    for (; i < e; i++){
        int c = __ldg(&cols[i]);
        float wv = __ldg(&ws[i]);
        float4 v = enc4[c*32 + lane];
        acc.x = fmaf(wv, v.x, acc.x);
        acc.y = fmaf(wv, v.y, acc.y);
        acc.z = fmaf(wv, v.z, acc.z);
        acc.w = fmaf(wv, v.w, acc.w);
    }
    agg4[row*32 + lane] = acc;
}

// ================= tf32 mma.sync GEMM + lrelu + row L2-norm =================
#define GP 132   // smem pitch in floats
__global__ void __launch_bounds__(256, 1)
k_gemm_tf32(const float4* __restrict__ X4, const float* __restrict__ W,
            const float* __restrict__ bias, float* __restrict__ Y, int M){
    extern __shared__ uint32_t sh[];
    uint32_t* As = sh;              // [128][GP] tf32 bits
    uint32_t* Bs = sh + 128*GP;     // [128][GP] tf32 bits
    __shared__ float ssred[128][4];
    __shared__ float sscale[128];
    int tid = threadIdx.x;
    int row0 = blockIdx.x * 128;

    const float4* W4 = (const float4*)W;
    for (int i = tid; i < 128*32; i += 256){
        int r = i >> 5, c4 = i & 31;
        int grow = row0 + r;
        float4 v = (grow < M) ? X4[grow*32 + c4] : make_float4(0.f,0.f,0.f,0.f);
        float4 wv = W4[i];
        int base = r*GP + c4*4;
        uint4 av = make_uint4(to_tf32(v.x),  to_tf32(v.y),  to_tf32(v.z),  to_tf32(v.w));
        uint4 bv = make_uint4(to_tf32(wv.x), to_tf32(wv.y), to_tf32(wv.z), to_tf32(wv.w));
        *(uint4*)&As[base] = av;
        *(uint4*)&Bs[base] = bv;
    }
    __syncthreads();

    int wid = tid >> 5, lane = tid & 31;
    int wm = wid & 1, wn = wid >> 1;
    int m_base = wm*64, n_base = wn*32;
    int qr = lane >> 2, qc = lane & 3;

    float acc[4][4][4];
    #pragma unroll
    for (int mi = 0; mi < 4; mi++)
        #pragma unroll
        for (int ni = 0; ni < 4; ni++)
            #pragma unroll
            for (int j = 0; j < 4; j++) acc[mi][ni][j] = 0.f;

    #pragma unroll 2
    for (int k0 = 0; k0 < 128; k0 += 8){
        uint32_t a[4][4];
        #pragma unroll
        for (int mi = 0; mi < 4; mi++){
            const uint32_t* ap = As + (m_base + mi*16 + qr)*GP + k0 + qc;
            a[mi][0] = ap[0];
            a[mi][1] = ap[8*GP];
            a[mi][2] = ap[4];
            a[mi][3] = ap[8*GP + 4];
        }
        uint32_t b[4][2];
        #pragma unroll
        for (int ni = 0; ni < 4; ni++){
            const uint32_t* bp = Bs + (n_base + ni*8 + qr)*GP + k0 + qc;
            b[ni][0] = bp[0];
            b[ni][1] = bp[4];
        }
        #pragma unroll
        for (int mi = 0; mi < 4; mi++)
            #pragma unroll
            for (int ni = 0; ni < 4; ni++)
                mma_tf32(acc[mi][ni], a[mi], b[ni]);
    }

    float2 bv[4];
    #pragma unroll
    for (int ni = 0; ni < 4; ni++)
        bv[ni] = *(const float2*)&bias[n_base + ni*8 + qc*2];

    float ss[4][2];
    #pragma unroll
    for (int mi = 0; mi < 4; mi++){ ss[mi][0] = 0.f; ss[mi][1] = 0.f; }
    #pragma unroll
    for (int mi = 0; mi < 4; mi++)
        #pragma unroll
        for (int ni = 0; ni < 4; ni++){
            float* d = acc[mi][ni];
            float t0 = d[0] + bv[ni].x, t1 = d[1] + bv[ni].y;
            float t2 = d[2] + bv[ni].x, t3 = d[3] + bv[ni].y;
            t0 = (t0 >= 0.f) ? t0 : 0.01f*t0;
            t1 = (t1 >= 0.f) ? t1 : 0.01f*t1;
            t2 = (t2 >= 0.f) ? t2 : 0.01f*t2;
            t3 = (t3 >= 0.f) ? t3 : 0.01f*t3;
            d[0] = t0; d[1] = t1; d[2] = t2; d[3] = t3;
            ss[mi][0] = fmaf(t0,t0, fmaf(t1,t1, ss[mi][0]));
            ss[mi][1] = fmaf(t2,t2, fmaf(t3,t3, ss[mi][1]));
        }
    #pragma unroll
    for (int mi = 0; mi < 4; mi++)
        #pragma unroll
        for (int hf = 0; hf < 2; hf++){
            float v = ss[mi][hf];
            v += __shfl_xor_sync(0xffffffffu, v, 1);
            v += __shfl_xor_sync(0xffffffffu, v, 2);
            if (qc == 0) ssred[m_base + mi*16 + qr + hf*8][wn] = v;
        }
    __syncthreads();
    if (tid < 128){
        float t = ssred[tid][0] + ssred[tid][1] + ssred[tid][2] + ssred[tid][3];
        sscale[tid] = 1.0f / fmaxf(sqrtf(t), 1e-12f);
    }
    __syncthreads();

    #pragma unroll
    for (int mi = 0; mi < 4; mi++){
        int lr0 = m_base + mi*16 + qr;
        int lr1 = lr0 + 8;
        float s0 = sscale[lr0], s1 = sscale[lr1];
        int r0 = row0 + lr0, r1 = row0 + lr1;
        #pragma unroll
        for (int ni = 0; ni < 4; ni++){
            float* d = acc[mi][ni];
            int col = n_base + ni*8 + qc*2;
            if (r0 < M) *(float2*)&Y[r0*DIM + col] = make_float2(d[0]*s0, d[1]*s0);
            if (r1 < M) *(float2*)&Y[r1*DIM + col] = make_float2(d[2]*s1, d[3]*s1);
        }
    }
}

// ---------------- QKV: scalar tiled GEMM ----------------
__global__ void __launch_bounds__(256, 1)
k_qkv2(const float4* __restrict__ enc4, const int* __restrict__ xidx,
       const float* __restrict__ inw, const float* __restrict__ inb,
       float4* __restrict__ qkv4){
    extern __shared__ float4 sh4[];
    float4* Xs = sh4;
    float4* Ws = sh4 + 4096;
    int tid = threadIdx.x;
    int row0 = blockIdx.x * 128;
    int nb = blockIdx.y;
    #pragma unroll
    for (int it = 0; it < 16; it++){
        int idx = tid + it*256;
        int m = idx >> 5, k4 = idx & 31;
        int src = __ldg(&xidx[row0 + m]);
        Xs[idx] = enc4[src*32 + k4];
    }
    const float4* W4 = (const float4*)(inw + nb*DIM*DIM);
    #pragma unroll
    for (int it = 0; it < 16; it++){
        int idx = tid + it*256;
        int n = idx >> 5, k4 = idx & 31;
        Ws[n*32 + (k4 ^ (n >> 3))] = W4[idx];
    }
    __syncthreads();

    int tx = tid & 15, ty = tid >> 4;
    float acc[8][8];
    #pragma unroll
    for (int r = 0; r < 8; r++)
        #pragma unroll
        for (int c = 0; c < 8; c++) acc[r][c] = 0.f;

    const float4* Xp = Xs + (ty*8)*32;
    const float4* Wp = Ws + (tx*8)*32;
    #pragma unroll 2
    for (int k4 = 0; k4 < 32; k4++){
        float4 xv[8], wv[8];
        #pragma unroll
        for (int r = 0; r < 8; r++) xv[r] = Xp[r*32 + k4];
        int ksw = k4 ^ tx;
        #pragma unroll
        for (int c = 0; c < 8; c++) wv[c] = Wp[c*32 + ksw];
        #pragma unroll
        for (int r = 0; r < 8; r++)
            #pragma unroll
            for (int c = 0; c < 8; c++){
                acc[r][c] = fmaf(xv[r].x, wv[c].x, acc[r][c]);
                acc[r][c] = fmaf(xv[r].y, wv[c].y, acc[r][c]);
                acc[r][c] = fmaf(xv[r].z, wv[c].z, acc[r][c]);
                acc[r][c] = fmaf(xv[r].w, wv[c].w, acc[r][c]);
            }
    }

    float bj[8];
    #pragma unroll
    for (int c = 0; c < 8; c++) bj[c] = __ldg(&inb[nb*DIM + tx*8 + c]);
    #pragma unroll
    for (int r = 0; r < 8; r++){
        int t = row0 + ty*8 + r;
        qkv4[t*96 + nb*32 + tx*2]     = make_float4(acc[r][0]+bj[0], acc[r][1]+bj[1], acc[r][2]+bj[2], acc[r][3]+bj[3]);
        qkv4[t*96 + nb*32 + tx*2 + 1] = make_float4(acc[r][4]+bj[4], acc[r][5]+bj[5], acc[r][6]+bj[6], acc[r][7]+bj[7]);
    }
}

// ---------------- attention: conflict-free rewrite, one block per (b, h) ----------------
// smem: sq[100][16], skT[16][100], sv[100][16], sp[100][100]  = 59200 B dynamic
__global__ void k_attn(const float* __restrict__ qkv, float* __restrict__ o){
    extern __shared__ float sha[];
    float* sq  = sha;                 // [100][16]
    float* skT = sha + LSEQ*16;       // [16][100]
    float* sv  = sha + 2*LSEQ*16;     // [100][16]
    float* sp  = sha + 3*LSEQ*16;     // [100][100]
    int b = blockIdx.x, h = blockIdx.y;
    int tid = threadIdx.x;
    for (int idx = tid; idx < LSEQ*16; idx += 128){
        int t = idx >> 4, d = idx & 15;
        int base = (b*LSEQ + t)*(3*DIM) + h*16 + d;
        sq[idx] = qkv[base];
        sv[idx] = qkv[base + 2*DIM];
    }
    for (int idx = tid; idx < LSEQ*16; idx += 128){
        int d = idx / LSEQ, t = idx - d*LSEQ;
        skT[idx] = qkv[(b*LSEQ + t)*(3*DIM) + DIM + h*16 + d];
    }
    __syncthreads();

    int lane = tid & 31, warp = tid >> 5;
    for (int qi = warp; qi < LSEQ; qi += 4){
        float q[16];
        #pragma unroll
        for (int d = 0; d < 16; d++) q[d] = sq[qi*16 + d];
        float v[4];
        float m = -1e30f;
        #pragma unroll
        for (int g = 0; g < 4; g++){
            int j = lane + g*32;
            float s = -1e30f;
            if (j < LSEQ){
                s = 0.f;
                #pragma unroll
                for (int d = 0; d < 16; d++) s = fmaf(q[d], skT[d*LSEQ + j], s);
                s *= 0.25f;   // 1/sqrt(16)
            }
            v[g] = s;
            m = fmaxf(m, s);
        }
        #pragma unroll
        for (int t = 16; t > 0; t >>= 1) m = fmaxf(m, __shfl_xor_sync(0xffffffffu, m, t));
        float ssum = 0.f;
        #pragma unroll
        for (int g = 0; g < 4; g++){
            int j = lane + g*32;
            float p = (j < LSEQ) ? __expf(v[g] - m) : 0.f;
            v[g] = p;
            ssum += p;
        }
        #pragma unroll
        for (int t = 16; t > 0; t >>= 1) ssum += __shfl_xor_sync(0xffffffffu, ssum, t);
        float inv = 1.0f / ssum;
        #pragma unroll
        for (int g = 0; g < 4; g++){
            int j = lane + g*32;
            if (j < LSEQ) sp[qi*LSEQ + j] = v[g]*inv;
        }
    }
    __syncthreads();

    // o phase: unit u = (qi, d4-group); 400 units
    const float4* sv4 = (const float4*)sv;
    for (int u = tid; u < LSEQ*4; u += 128){
        int qi = u >> 2, dg = u & 3;
        float4 acc = make_float4(0.f,0.f,0.f,0.f);
        const float* pp = sp + qi*LSEQ;
        #pragma unroll 4
        for (int j = 0; j < LSEQ; j++){
            float p = pp[j];
            float4 vv = sv4[j*4 + dg];
            acc.x = fmaf(p, vv.x, acc.x);
            acc.y = fmaf(p, vv.y, acc.y);
            acc.z = fmaf(p, vv.z, acc.z);
            acc.w = fmaf(p, vv.w, acc.w);
        }
        *(float4*)&o[(b*LSEQ + qi)*DIM + h*16 + dg*4] = acc;
    }
}

// ---------------- mean over L + out-projection + target gather ----------------
__global__ void k_tail(const float* __restrict__ o, const float* __restrict__ ow,
                       const float* __restrict__ ob, const float* __restrict__ enc,
                       const int* __restrict__ pidx, float* __restrict__ out){
    __shared__ float sx[DIM];
    int b = blockIdx.x, j = threadIdx.x;
    float s = 0.0f;
    for (int i = 0; i < LSEQ; i++) s += o[(b*LSEQ + i)*DIM + j];
    sx[j] = s * (1.0f/LSEQ);
    __syncthreads();
    float acc = ob[j];
    #pragma unroll 4
    for (int k = 0; k < DIM; k++) acc += sx[k]*ow[j*DIM + k];
    out[b*DIM + j] = acc;
    out[BATCH*DIM + b*DIM + j] = enc[pidx[b]*DIM + j];
}

// ---------------- host launch ----------------
extern "C" void kernel_launch(void* const* d_in, const int* in_sizes, int n_in,
                              void* d_out, int out_size){
    const float* embeds = (const float*)d_in[0];
    const float* gcnW   = (const float*)d_in[1];
    const float* gcnb   = (const float*)d_in[2];
    const float* inw    = (const float*)d_in[3];
    const float* inb    = (const float*)d_in[4];
    const float* ow     = (const float*)d_in[5];
    const float* ob     = (const float*)d_in[6];
    const float* dv     = (const float*)d_in[7];
    const int*   edges  = (const int*)d_in[8];
    const int*   xidx   = (const int*)d_in[9];
    const int*   pidx   = (const int*)d_in[10];
    const int* e0 = edges;
    const int* e1 = edges + E_EDGES;
    float* out = (float*)d_out;

    int *cnt, *rowptr, *rowcur, *colidx;
    float *dis, *wcsr, *agg, *bA, *bB, *qkv, *obuf;
    cudaGetSymbolAddress((void**)&cnt,    g_cnt);
    cudaGetSymbolAddress((void**)&rowptr, g_rowptr);
    cudaGetSymbolAddress((void**)&rowcur, g_rowcur);
    cudaGetSymbolAddress((void**)&dis,    g_dis);
    cudaGetSymbolAddress((void**)&colidx, g_colidx);
    cudaGetSymbolAddress((void**)&wcsr,   g_wcsr);
    cudaGetSymbolAddress((void**)&agg,    g_agg);
    cudaGetSymbolAddress((void**)&bA,     g_bufA);
    cudaGetSymbolAddress((void**)&bB,     g_bufB);
    cudaGetSymbolAddress((void**)&qkv,    g_qkv);
    cudaGetSymbolAddress((void**)&obuf,   g_o);

    const int smem_qkv  = 2*4096*(int)sizeof(float4);      // 131072
    const int smem_gemm = 2*128*GP*(int)sizeof(uint32_t);  // 135168
    const int smem_attn = (3*LSEQ*16 + LSEQ*LSEQ)*(int)sizeof(float);  // 59200
    cudaFuncSetAttribute(k_gemm_tf32, cudaFuncAttributeMaxDynamicSharedMemorySize, smem_gemm);
    cudaFuncSetAttribute(k_qkv2,      cudaFuncAttributeMaxDynamicSharedMemorySize, smem_qkv);
    cudaFuncSetAttribute(k_attn,      cudaFuncAttributeMaxDynamicSharedMemorySize, smem_attn);

    // CSR build
    k_zero_cnt<<<(N_POI+255)/256, 256>>>(cnt);
    k_hist<<<(E_EDGES+255)/256, 256>>>(e0, e1, cnt);
    k_scan<<<1, 1024>>>(cnt, rowptr, rowcur, dis);
    k_scatter<<<(E_EDGES+255)/256, 256>>>(e0, e1, dv, dis, rowcur, colidx, wcsr);

    // 3 GCN layers
    const float* enc_in = embeds;
    float* outs[GCN_NUM] = {bA, bB, bA};
    for (int i = 0; i < GCN_NUM; i++){
        k_spmm2<<<(N_POI+7)/8, 256>>>((const float4*)enc_in, rowptr, colidx, wcsr, dis,
                                       (float4*)agg);
        k_gemm_tf32<<<(N_POI+127)/128, 256, smem_gemm>>>(
            (const float4*)agg, gcnW + i*DIM*DIM, gcnb + i*DIM, outs[i], N_POI);
        enc_in = outs[i];
    }
    const float* encF = enc_in;  // g_bufA

    // attention
    k_qkv2<<<dim3(NTOK/128, 3), 256, smem_qkv>>>((const float4*)encF, xidx, inw, inb,
                                                 (float4*)qkv);
    k_attn<<<dim3(BATCH, 8), 128, smem_attn>>>(qkv, obuf);
    k_tail<<<BATCH, 128>>>(obuf, ow, ob, encF, pidx, out);
}

// round 7
// speedup vs baseline: 1.2108x; 1.0039x over previous
#include <cuda_runtime.h>
#include <cuda_fp16.h>
#include <math.h>
#include <stdint.h>

#define N_POI 50000
#define DIM 128
#define E_EDGES 400000
#define GCN_NUM 3
#define BATCH 64
#define LSEQ 100
#define NTOK (BATCH*LSEQ)
#define DIRE (2*E_EDGES)

// ---------------- device scratch (static, no allocations) ----------------
__device__ __align__(16) int    g_cnt[N_POI];
__device__ __align__(16) int    g_rowptr[N_POI+1];
__device__ __align__(16) int    g_rowcur[N_POI];
__device__ __align__(16) float  g_dis[N_POI];
__device__ __align__(16) int    g_colidx[DIRE];
__device__ __align__(16) float  g_wcsr[DIRE];
__device__ __align__(16) float  g_bufA[N_POI*DIM];
__device__ __align__(16) float  g_agg[N_POI*DIM];
__device__ __align__(16) __half g_encH[N_POI*DIM];   // fp16 mirror for SpMM gather
__device__ __align__(16) float  g_qkv[NTOK*3*DIM];
__device__ __align__(16) float  g_o[NTOK*DIM];

// tf32 helpers (base-target safe: mma.sync is sm_80+ PTX)
__device__ __forceinline__ uint32_t to_tf32(float x){
    uint32_t u;
    asm("cvt.rna.tf32.f32 %0, %1;" : "=r"(u) : "f"(x));
    return u;
}
__device__ __forceinline__ void mma_tf32(float* d, const uint32_t* a, const uint32_t* b){
    asm volatile("mma.sync.aligned.m16n8k8.row.col.f32.tf32.tf32.f32 "
        "{%0,%1,%2,%3}, {%4,%5,%6,%7}, {%8,%9}, {%0,%1,%2,%3};"
        : "+f"(d[0]), "+f"(d[1]), "+f"(d[2]), "+f"(d[3])
        : "r"(a[0]), "r"(a[1]), "r"(a[2]), "r"(a[3]), "r"(b[0]), "r"(b[1]));
}

// ---------------- CSR build ----------------
__global__ void k_hist(const int* __restrict__ e0, const int* __restrict__ e1, int* cnt){
    int e = blockIdx.x*256 + threadIdx.x;
    if (e < E_EDGES){
        atomicAdd(&cnt[e0[e]], 1);
        atomicAdd(&cnt[e1[e]], 1);
    }
}
__global__ void k_scan(const int* __restrict__ cnt, int* __restrict__ rowptr,
                       int* __restrict__ rowcur, float* __restrict__ dis){
    __shared__ int sh[1024];
    int t = threadIdx.x;
    const int CH = (N_POI + 1023)/1024;
    int base = t*CH;
    int s = 0;
    for (int i = 0; i < CH; i++){
        int idx = base + i;
        if (idx < N_POI) s += cnt[idx];
    }
    sh[t] = s;
    __syncthreads();
    for (int o = 1; o < 1024; o <<= 1){
        int v = (t >= o) ? sh[t-o] : 0;
        __syncthreads();
        sh[t] += v;
        __syncthreads();
    }
    int off = (t == 0) ? 0 : sh[t-1];
    for (int i = 0; i < CH; i++){
        int idx = base + i;
        if (idx < N_POI){
            int c = cnt[idx];
            rowptr[idx] = off;
            rowcur[idx] = off;
            dis[idx] = rsqrtf((float)(c + 1));
            off += c;
        }
    }
    if (t == 1023) rowptr[N_POI] = sh[1023];
}
__global__ void k_scatter(const int* __restrict__ e0, const int* __restrict__ e1,
                          const float* __restrict__ dv, const float* __restrict__ dis,
                          int* rowcur, int* __restrict__ colidx, float* __restrict__ wcsr){
    int e = blockIdx.x*256 + threadIdx.x;
    if (e >= E_EDGES) return;
    int a = e0[e], b = e1[e];
    float d = dv[e];
    float wv = expf(-d*d) * dis[a] * dis[b];
    int p = atomicAdd(&rowcur[a], 1);
    colidx[p] = b; wcsr[p] = wv;
    p = atomicAdd(&rowcur[b], 1);
    colidx[p] = a; wcsr[p] = wv;
}

// ---------------- embeds -> fp16 mirror (layer-1 input) ----------------
__global__ void k_cvt_h(const float4* __restrict__ x4, __half* __restrict__ yh, int n4){
    int i = blockIdx.x*256 + threadIdx.x;
    if (i < n4){
        float4 v = x4[i];
        ((__half2*)yh)[i*2]     = __floats2half2_rn(v.x, v.y);
        ((__half2*)yh)[i*2 + 1] = __floats2half2_rn(v.z, v.w);
    }
}

// ---------------- SpMM: fp16 row gather (one warp per row), fp32 accumulate ----------------
// lane handles cols [4*lane, 4*lane+4): one uint2 (4 halves) per row.
__global__ void k_spmm2(const uint2* __restrict__ encH2, const int* __restrict__ rowptr,
                        const int* __restrict__ cols, const float* __restrict__ ws,
                        const float* __restrict__ dis, float4* __restrict__ agg4){
    int row = blockIdx.x*8 + (threadIdx.x >> 5);
    int lane = threadIdx.x & 31;
    if (row >= N_POI) return;
    float ds = dis[row];
    float sl = ds*ds;

    uint2 xs = encH2[row*32 + lane];
    float2 xa = __half22float2(*(const __half2*)&xs.x);
    float2 xb = __half22float2(*(const __half2*)&xs.y);
    float4 acc = make_float4(sl*xa.x, sl*xa.y, sl*xb.x, sl*xb.y);

    int s = __ldg(&rowptr[row]), e = __ldg(&rowptr[row+1]);
    int i = s;
    for (; i + 4 <= e; i += 4){
        int c0 = __ldg(&cols[i]),   c1 = __ldg(&cols[i+1]);
        int c2 = __ldg(&cols[i+2]), c3 = __ldg(&cols[i+3]);
        float w0 = __ldg(&ws[i]),   w1 = __ldg(&ws[i+1]);
        float w2 = __ldg(&ws[i+2]), w3 = __ldg(&ws[i+3]);
        uint2 u0 = encH2[c0*32 + lane];
        uint2 u1 = encH2[c1*32 + lane];
        uint2 u2 = encH2[c2*32 + lane];
        uint2 u3 = encH2[c3*32 + lane];
        float2 a0 = __half22float2(*(const __half2*)&u0.x), b0 = __half22float2(*(const __half2*)&u0.y);
        float2 a1 = __half22float2(*(const __half2*)&u1.x), b1 = __half22float2(*(const __half2*)&u1.y);
        float2 a2 = __half22float2(*(const __half2*)&u2.x), b2 = __half22float2(*(const __half2*)&u2.y);
        float2 a3 = __half22float2(*(const __half2*)&u3.x), b3 = __half22float2(*(const __half2*)&u3.y);
        acc.x = fmaf(w3,a3.x, fmaf(w2,a2.x, fmaf(w1,a1.x, fmaf(w0,a0.x, acc.x))));
        acc.y = fmaf(w3,a3.y, fmaf(w2,a2.y, fmaf(w1,a1.y, fmaf(w0,a0.y, acc.y))));
        acc.z = fmaf(w3,b3.x, fmaf(w2,b2.x, fmaf(w1,b1.x, fmaf(w0,b0.x, acc.z))));
        acc.w = fmaf(w3,b3.y, fmaf(w2,b2.y, fmaf(w1,b1.y, fmaf(w0,b0.y, acc.w))));
    }
    for (; i < e; i++){
        int c = __ldg(&cols[i]);
        float wv = __ldg(&ws[i]);
        uint2 u = encH2[c*32 + lane];
        float2 a = __half22float2(*(const __half2*)&u.x);
        float2 b = __half22float2(*(const __half2*)&u.y);
        acc.x = fmaf(wv, a.x, acc.x);
        acc.y = fmaf(wv, a.y, acc.y);
        acc.z = fmaf(wv, b.x, acc.z);
        acc.w = fmaf(wv, b.y, acc.w);
    }
    agg4[row*32 + lane] = acc;
}

// ================= tf32 mma.sync GEMM + lrelu + row L2-norm =================
// writes fp32 Y and fp16 mirror Yh
#define GP 132
__global__ void __launch_bounds__(256, 1)
k_gemm_tf32(const float4* __restrict__ X4, const float* __restrict__ W,
            const float* __restrict__ bias, float* __restrict__ Y,
            __half2* __restrict__ Yh2, int M){
    extern __shared__ uint32_t sh[];
    uint32_t* As = sh;
    uint32_t* Bs = sh + 128*GP;
    __shared__ float ssred[128][4];
    __shared__ float sscale[128];
    int tid = threadIdx.x;
    int row0 = blockIdx.x * 128;

    const float4* W4 = (const float4*)W;
    for (int i = tid; i < 128*32; i += 256){
        int r = i >> 5, c4 = i & 31;
        int grow = row0 + r;
        float4 v = (grow < M) ? X4[grow*32 + c4] : make_float4(0.f,0.f,0.f,0.f);
        float4 wv = W4[i];
        int base = r*GP + c4*4;
        uint4 av = make_uint4(to_tf32(v.x),  to_tf32(v.y),  to_tf32(v.z),  to_tf32(v.w));
        uint4 bv = make_uint4(to_tf32(wv.x), to_tf32(wv.y), to_tf32(wv.z), to_tf32(wv.w));
        *(uint4*)&As[base] = av;
        *(uint4*)&Bs[base] = bv;
    }
    __syncthreads();

    int wid = tid >> 5, lane = tid & 31;
    int wm = wid & 1, wn = wid >> 1;
    int m_base = wm*64, n_base = wn*32;
    int qr = lane >> 2, qc = lane & 3;

    float acc[4][4][4];
    #pragma unroll
    for (int mi = 0; mi < 4; mi++)
        #pragma unroll
        for (int ni = 0; ni < 4; ni++)
            #pragma unroll
            for (int j = 0; j < 4; j++) acc[mi][ni][j] = 0.f;

    #pragma unroll 2
    for (int k0 = 0; k0 < 128; k0 += 8){
        uint32_t a[4][4];
        #pragma unroll
        for (int mi = 0; mi < 4; mi++){
            const uint32_t* ap = As + (m_base + mi*16 + qr)*GP + k0 + qc;
            a[mi][0] = ap[0];
            a[mi][1] = ap[8*GP];
            a[mi][2] = ap[4];
            a[mi][3] = ap[8*GP + 4];
        }
        uint32_t b[4][2];
        #pragma unroll
        for (int ni = 0; ni < 4; ni++){
            const uint32_t* bp = Bs + (n_base + ni*8 + qr)*GP + k0 + qc;
            b[ni][0] = bp[0];
            b[ni][1] = bp[4];
        }
        #pragma unroll
        for (int mi = 0; mi < 4; mi++)
            #pragma unroll
            for (int ni = 0; ni < 4; ni++)
                mma_tf32(acc[mi][ni], a[mi], b[ni]);
    }

    float2 bv[4];
    #pragma unroll
    for (int ni = 0; ni < 4; ni++)
        bv[ni] = *(const float2*)&bias[n_base + ni*8 + qc*2];

    float ss[4][2];
    #pragma unroll
    for (int mi = 0; mi < 4; mi++){ ss[mi][0] = 0.f; ss[mi][1] = 0.f; }
    #pragma unroll
    for (int mi = 0; mi < 4; mi++)
        #pragma unroll
        for (int ni = 0; ni < 4; ni++){
            float* d = acc[mi][ni];
            float t0 = d[0] + bv[ni].x, t1 = d[1] + bv[ni].y;
            float t2 = d[2] + bv[ni].x, t3 = d[3] + bv[ni].y;
            t0 = (t0 >= 0.f) ? t0 : 0.01f*t0;
            t1 = (t1 >= 0.f) ? t1 : 0.01f*t1;
            t2 = (t2 >= 0.f) ? t2 : 0.01f*t2;
            t3 = (t3 >= 0.f) ? t3 : 0.01f*t3;
            d[0] = t0; d[1] = t1; d[2] = t2; d[3] = t3;
            ss[mi][0] = fmaf(t0,t0, fmaf(t1,t1, ss[mi][0]));
            ss[mi][1] = fmaf(t2,t2, fmaf(t3,t3, ss[mi][1]));
        }
    #pragma unroll
    for (int mi = 0; mi < 4; mi++)
        #pragma unroll
        for (int hf = 0; hf < 2; hf++){
            float v = ss[mi][hf];
            v += __shfl_xor_sync(0xffffffffu, v, 1);
            v += __shfl_xor_sync(0xffffffffu, v, 2);
            if (qc == 0) ssred[m_base + mi*16 + qr + hf*8][wn] = v;
        }
    __syncthreads();
    if (tid < 128){
        float t = ssred[tid][0] + ssred[tid][1] + ssred[tid][2] + ssred[tid][3];
        sscale[tid] = 1.0f / fmaxf(sqrtf(t), 1e-12f);
    }
    __syncthreads();

    #pragma unroll
    for (int mi = 0; mi < 4; mi++){
        int lr0 = m_base + mi*16 + qr;
        int lr1 = lr0 + 8;
        float s0 = sscale[lr0], s1 = sscale[lr1];
        int r0 = row0 + lr0, r1 = row0 + lr1;
        #pragma unroll
        for (int ni = 0; ni < 4; ni++){
            float* d = acc[mi][ni];
            int col = n_base + ni*8 + qc*2;
            if (r0 < M){
                float y0 = d[0]*s0, y1 = d[1]*s0;
                *(float2*)&Y[r0*DIM + col] = make_float2(y0, y1);
                Yh2[r0*64 + (col >> 1)] = __floats2half2_rn(y0, y1);
            }
            if (r1 < M){
                float y2 = d[2]*s1, y3 = d[3]*s1;
                *(float2*)&Y[r1*DIM + col] = make_float2(y2, y3);
                Yh2[r1*64 + (col >> 1)] = __floats2half2_rn(y2, y3);
            }
        }
    }
}

// ---------------- QKV: scalar tiled GEMM ----------------
__global__ void __launch_bounds__(256, 1)
k_qkv2(const float4* __restrict__ enc4, const int* __restrict__ xidx,
       const float* __restrict__ inw, const float* __restrict__ inb,
       float4* __restrict__ qkv4){
    extern __shared__ float4 sh4[];
    float4* Xs = sh4;
    float4* Ws = sh4 + 4096;
    int tid = threadIdx.x;
    int row0 = blockIdx.x * 128;
    int nb = blockIdx.y;
    #pragma unroll
    for (int it = 0; it < 16; it++){
        int idx = tid + it*256;
        int m = idx >> 5, k4 = idx & 31;
        int src = __ldg(&xidx[row0 + m]);
        Xs[idx] = enc4[src*32 + k4];
    }
    const float4* W4 = (const float4*)(inw + nb*DIM*DIM);
    #pragma unroll
    for (int it = 0; it < 16; it++){
        int idx = tid + it*256;
        int n = idx >> 5, k4 = idx & 31;
        Ws[n*32 + (k4 ^ (n >> 3))] = W4[idx];
    }
    __syncthreads();

    int tx = tid & 15, ty = tid >> 4;
    float acc[8][8];
    #pragma unroll
    for (int r = 0; r < 8; r++)
        #pragma unroll
        for (int c = 0; c < 8; c++) acc[r][c] = 0.f;

    const float4* Xp = Xs + (ty*8)*32;
    const float4* Wp = Ws + (tx*8)*32;
    #pragma unroll 2
    for (int k4 = 0; k4 < 32; k4++){
        float4 xv[8], wv[8];
        #pragma unroll
        for (int r = 0; r < 8; r++) xv[r] = Xp[r*32 + k4];
        int ksw = k4 ^ tx;
        #pragma unroll
        for (int c = 0; c < 8; c++) wv[c] = Wp[c*32 + ksw];
        #pragma unroll
        for (int r = 0; r < 8; r++)
            #pragma unroll
            for (int c = 0; c < 8; c++){
                acc[r][c] = fmaf(xv[r].x, wv[c].x, acc[r][c]);
                acc[r][c] = fmaf(xv[r].y, wv[c].y, acc[r][c]);
                acc[r][c] = fmaf(xv[r].z, wv[c].z, acc[r][c]);
                acc[r][c] = fmaf(xv[r].w, wv[c].w, acc[r][c]);
            }
    }

    float bj[8];
    #pragma unroll
    for (int c = 0; c < 8; c++) bj[c] = __ldg(&inb[nb*DIM + tx*8 + c]);
    #pragma unroll
    for (int r = 0; r < 8; r++){
        int t = row0 + ty*8 + r;
        qkv4[t*96 + nb*32 + tx*2]     = make_float4(acc[r][0]+bj[0], acc[r][1]+bj[1], acc[r][2]+bj[2], acc[r][3]+bj[3]);
        qkv4[t*96 + nb*32 + tx*2 + 1] = make_float4(acc[r][4]+bj[4], acc[r][5]+bj[5], acc[r][6]+bj[6], acc[r][7]+bj[7]);
    }
}

// ---------------- attention: conflict-free, one block per (b, h) ----------------
__global__ void k_attn(const float* __restrict__ qkv, float* __restrict__ o){
    extern __shared__ float sha[];
    float* sq  = sha;
    float* skT = sha + LSEQ*16;
    float* sv  = sha + 2*LSEQ*16;
    float* sp  = sha + 3*LSEQ*16;
    int b = blockIdx.x, h = blockIdx.y;
    int tid = threadIdx.x;
    for (int idx = tid; idx < LSEQ*16; idx += 128){
        int t = idx >> 4, d = idx & 15;
        int base = (b*LSEQ + t)*(3*DIM) + h*16 + d;
        sq[idx] = qkv[base];
        sv[idx] = qkv[base + 2*DIM];
    }
    for (int idx = tid; idx < LSEQ*16; idx += 128){
        int d = idx / LSEQ, t = idx - d*LSEQ;
        skT[idx] = qkv[(b*LSEQ + t)*(3*DIM) + DIM + h*16 + d];
    }
    __syncthreads();

    int lane = tid & 31, warp = tid >> 5;
    for (int qi = warp; qi < LSEQ; qi += 4){
        float q[16];
        #pragma unroll
        for (int d = 0; d < 16; d++) q[d] = sq[qi*16 + d];
        float v[4];
        float m = -1e30f;
        #pragma unroll
        for (int g = 0; g < 4; g++){
            int j = lane + g*32;
            float s = -1e30f;
            if (j < LSEQ){
                s = 0.f;
                #pragma unroll
                for (int d = 0; d < 16; d++) s = fmaf(q[d], skT[d*LSEQ + j], s);
                s *= 0.25f;
            }
            v[g] = s;
            m = fmaxf(m, s);
        }
        #pragma unroll
        for (int t = 16; t > 0; t >>= 1) m = fmaxf(m, __shfl_xor_sync(0xffffffffu, m, t));
        float ssum = 0.f;
        #pragma unroll
        for (int g = 0; g < 4; g++){
            int j = lane + g*32;
            float p = (j < LSEQ) ? __expf(v[g] - m) : 0.f;
            v[g] = p;
            ssum += p;
        }
        #pragma unroll
        for (int t = 16; t > 0; t >>= 1) ssum += __shfl_xor_sync(0xffffffffu, ssum, t);
        float inv = 1.0f / ssum;
        #pragma unroll
        for (int g = 0; g < 4; g++){
            int j = lane + g*32;
            if (j < LSEQ) sp[qi*LSEQ + j] = v[g]*inv;
        }
    }
    __syncthreads();

    const float4* sv4 = (const float4*)sv;
    for (int u = tid; u < LSEQ*4; u += 128){
        int qi = u >> 2, dg = u & 3;
        float4 acc = make_float4(0.f,0.f,0.f,0.f);
        const float* pp = sp + qi*LSEQ;
        #pragma unroll 4
        for (int j = 0; j < LSEQ; j++){
            float p = pp[j];
            float4 vv = sv4[j*4 + dg];
            acc.x = fmaf(p, vv.x, acc.x);
            acc.y = fmaf(p, vv.y, acc.y);
            acc.z = fmaf(p, vv.z, acc.z);
            acc.w = fmaf(p, vv.w, acc.w);
        }
        *(float4*)&o[(b*LSEQ + qi)*DIM + h*16 + dg*4] = acc;
    }
}

// ---------------- mean over L + out-projection + target gather ----------------
__global__ void k_tail(const float* __restrict__ o, const float* __restrict__ ow,
                       const float* __restrict__ ob, const float* __restrict__ enc,
                       const int* __restrict__ pidx, float* __restrict__ out){
    __shared__ float sx[DIM];
    int b = blockIdx.x, j = threadIdx.x;
    float s = 0.0f;
    for (int i = 0; i < LSEQ; i++) s += o[(b*LSEQ + i)*DIM + j];
    sx[j] = s * (1.0f/LSEQ);
    __syncthreads();
    float acc = ob[j];
    #pragma unroll 4
    for (int k = 0; k < DIM; k++) acc += sx[k]*ow[j*DIM + k];
    out[b*DIM + j] = acc;
    out[BATCH*DIM + b*DIM + j] = enc[pidx[b]*DIM + j];
}

// ---------------- host launch ----------------
extern "C" void kernel_launch(void* const* d_in, const int* in_sizes, int n_in,
                              void* d_out, int out_size){
    const float* embeds = (const float*)d_in[0];
    const float* gcnW   = (const float*)d_in[1];
    const float* gcnb   = (const float*)d_in[2];
    const float* inw    = (const float*)d_in[3];
    const float* inb    = (const float*)d_in[4];
    const float* ow     = (const float*)d_in[5];
    const float* ob     = (const float*)d_in[6];
    const float* dv     = (const float*)d_in[7];
    const int*   edges  = (const int*)d_in[8];
    const int*   xidx   = (const int*)d_in[9];
    const int*   pidx   = (const int*)d_in[10];
    const int* e0 = edges;
    const int* e1 = edges + E_EDGES;
    float* out = (float*)d_out;

    int *cnt, *rowptr, *rowcur, *colidx;
    float *dis, *wcsr, *agg, *bA, *qkv, *obuf;
    __half* encH;
    cudaGetSymbolAddress((void**)&cnt,    g_cnt);
    cudaGetSymbolAddress((void**)&rowptr, g_rowptr);
    cudaGetSymbolAddress((void**)&rowcur, g_rowcur);
    cudaGetSymbolAddress((void**)&dis,    g_dis);
    cudaGetSymbolAddress((void**)&colidx, g_colidx);
    cudaGetSymbolAddress((void**)&wcsr,   g_wcsr);
    cudaGetSymbolAddress((void**)&agg,    g_agg);
    cudaGetSymbolAddress((void**)&bA,     g_bufA);
    cudaGetSymbolAddress((void**)&encH,   g_encH);
    cudaGetSymbolAddress((void**)&qkv,    g_qkv);
    cudaGetSymbolAddress((void**)&obuf,   g_o);

    const int smem_qkv  = 2*4096*(int)sizeof(float4);
    const int smem_gemm = 2*128*GP*(int)sizeof(uint32_t);
    const int smem_attn = (3*LSEQ*16 + LSEQ*LSEQ)*(int)sizeof(float);
    cudaFuncSetAttribute(k_gemm_tf32, cudaFuncAttributeMaxDynamicSharedMemorySize, smem_gemm);
    cudaFuncSetAttribute(k_qkv2,      cudaFuncAttributeMaxDynamicSharedMemorySize, smem_qkv);
    cudaFuncSetAttribute(k_attn,      cudaFuncAttributeMaxDynamicSharedMemorySize, smem_attn);

    // CSR build + fp16 mirror of embeds (independent work, same stream)
    cudaMemsetAsync(cnt, 0, N_POI*sizeof(int));
    k_hist<<<(E_EDGES+255)/256, 256>>>(e0, e1, cnt);
    k_cvt_h<<<(N_POI*32+255)/256, 256>>>((const float4*)embeds, encH, N_POI*32);
    k_scan<<<1, 1024>>>(cnt, rowptr, rowcur, dis);
    k_scatter<<<(E_EDGES+255)/256, 256>>>(e0, e1, dv, dis, rowcur, colidx, wcsr);

    // 3 GCN layers: SpMM gathers fp16 mirror; GEMM writes fp32 (bA) + fp16 mirror
    for (int i = 0; i < GCN_NUM; i++){
        k_spmm2<<<(N_POI+7)/8, 256>>>((const uint2*)encH, rowptr, colidx, wcsr, dis,
                                       (float4*)agg);
        k_gemm_tf32<<<(N_POI+127)/128, 256, smem_gemm>>>(
            (const float4*)agg, gcnW + i*DIM*DIM, gcnb + i*DIM, bA, (__half2*)encH, N_POI);
    }
    const float* encF = bA;

    // attention
    k_qkv2<<<dim3(NTOK/128, 3), 256, smem_qkv>>>((const float4*)encF, xidx, inw, inb,
                                                 (float4*)qkv);
    k_attn<<<dim3(BATCH, 8), 128, smem_attn>>>(qkv, obuf);
    k_tail<<<BATCH, 128>>>(obuf, ow, ob, encF, pidx, out);
}